// round 14
// baseline (speedup 1.0000x reference)
#include <cuda_runtime.h>
#include <cuda_bf16.h>
#include <math_constants.h>

#define B_  256
#define S_  128
#define D_  768
#define MASK_ID_ 103
#define NB  296          // persistent grid: 2 CTAs/SM on 148 SMs (residency proven in R11)
#define NT  512          // 16 warps per CTA -> 32 warps/SM

// Scratch (no allocation allowed -> device globals)
__device__ float g_feats[B_ * 2 * D_];   // [att | mask_logits], 256 x 1536
__device__ float g_h[B_ * D_];           // tanh(dense) output, 256 x 768
__device__ float g_sraw[B_ * S_];        // raw scores, 256 x 128
__device__ unsigned int g_count;         // monotonic grid-barrier counter (replay-safe)

__constant__ int c_label_ids[21] = {
    2307, 2204, 3835, 2157, 6581, 2986, 5151, 3893,
    7929, 24791, 8699, 4257, 16021, 6623,
    6659, 2919, 11771, 3532, 11325, 4997, 13135
};

__device__ __forceinline__ float warp_sum(float v) {
    #pragma unroll
    for (int o = 16; o; o >>= 1) v += __shfl_xor_sync(0xffffffffu, v, o);
    return v;
}
__device__ __forceinline__ float warp_max(float v) {
    #pragma unroll
    for (int o = 16; o; o >>= 1) v = fmaxf(v, __shfl_xor_sync(0xffffffffu, v, o));
    return v;
}

#define FMA_F32X2(acc, a, b) \
    asm("fma.rn.f32x2 %0, %1, %2, %0;" : "+l"(acc) : "l"(a), "l"(b))

__device__ __forceinline__ float dot4(float4 a, float4 b, float acc) {
    return fmaf(a.x, b.x, fmaf(a.y, b.y, fmaf(a.z, b.z, fmaf(a.w, b.w, acc))));
}

// Grid-wide barrier: monotonic counter, no reset -> safe across graph replays.
__device__ __forceinline__ void grid_barrier() {
    __syncthreads();
    if (threadIdx.x == 0) {
        __threadfence();
        unsigned int my = atomicAdd(&g_count, 1u) + 1u;
        unsigned int target = ((my + NB - 1u) / NB) * NB;
        while (*((volatile unsigned int*)&g_count) < target) __nanosleep(64);
        __threadfence();
    }
    __syncthreads();
}

#define BK 32
#define KDIM 1536
#define NDIM 768

struct SmemP1 { float ml[D_]; int mpos; };
struct SmemP2 { float sc[S_]; float red[2]; };
struct SmemP3 { unsigned long long As2u[BK * 17]; unsigned long long Bsdu[BK * 49]; };
struct SmemP4 { float hs[D_]; float probs[21]; };

// ---------------------------------------------------------------------------
// ONE persistent kernel, 4 phases separated by grid barriers.
// 512 threads x 296 CTAs: 32 warps/SM at only 2 CTAs/SM residency.
// ---------------------------------------------------------------------------
__global__ __launch_bounds__(NT, 2) void fused_all(
    const float* __restrict__ bert,
    const int*   __restrict__ input_ids,
    const int*   __restrict__ length,
    const float* __restrict__ senti_w,
    const float* __restrict__ senti_b,
    const float* __restrict__ dense_w,
    const float* __restrict__ dense_b,
    const float* __restrict__ dec_w,
    const float* __restrict__ dec_b,
    const float* __restrict__ w0,
    const float* __restrict__ w1,
    const float* __restrict__ w2,
    float*       __restrict__ d_out,
    float*       __restrict__ feats,
    float*       __restrict__ hbuf,
    float*       __restrict__ sraw)
{
    __shared__ union { SmemP1 p1; SmemP2 p2; SmemP3 p3; SmemP4 p4; } sm;

    const int tid  = threadIdx.x;
    const int warp = tid >> 5;
    const int lane = tid & 31;

    // ============ Phase 1: scores_raw = bert . mask_logits =================
    // item = (b, chunk of 16 rows): 256*8 = 2048 items; one row per warp,
    // 6 independent LDG.128 in flight per warp, 32 warps/SM.
    for (int it = blockIdx.x; it < B_ * 8; it += NB) {
        const int b     = it >> 3;
        const int chunk = it & 7;
        const float* base = bert + (size_t)b * (S_ * D_);

        __syncthreads();                       // protect smem reuse
        if (tid == 0) sm.p1.mpos = 0x7fffffff;
        __syncthreads();
        if (tid < S_ && input_ids[b * S_ + tid] == MASK_ID_)
            atomicMin(&sm.p1.mpos, tid);
        __syncthreads();
        const int mp = sm.p1.mpos;

        float4* ml4 = (float4*)sm.p1.ml;
        if (tid < 192) {
            float4 v = ((const float4*)(base + (size_t)mp * D_))[tid];
            ml4[tid] = v;
            if (chunk == 0)
                ((float4*)(feats + (size_t)b * (2 * D_) + D_))[tid] = v;
        }
        __syncthreads();

        const int s = chunk * 16 + warp;
        const float4* r4 = (const float4*)(base + (size_t)s * D_);

        float4 v0 = r4[lane];
        float4 v1 = r4[lane + 32];
        float4 v2 = r4[lane + 64];
        float4 v3 = r4[lane + 96];
        float4 v4 = r4[lane + 128];
        float4 v5 = r4[lane + 160];

        float a = 0.f;
        a = dot4(v0, ml4[lane],       a);
        a = dot4(v1, ml4[lane + 32],  a);
        a = dot4(v2, ml4[lane + 64],  a);
        a = dot4(v3, ml4[lane + 96],  a);
        a = dot4(v4, ml4[lane + 128], a);
        a = dot4(v5, ml4[lane + 160], a);
        a = warp_sum(a);
        if (lane == 0) sraw[b * S_ + s] = a;
    }

    grid_barrier();

    // ============ Phase 2: softmax + att; feats[b][0:D] = att ==============
    // item = b (256 items). Thread t covers dim t (all 512) and dim t+512
    // (t < 256). 8-deep load batches, 32 warps/SM in flight.
    for (int it = blockIdx.x; it < B_; it += NB) {
        const int b = it;

        __syncthreads();                       // protect sc reuse
        if (tid < S_) sm.p2.sc[tid] = __ldcg(sraw + b * S_ + tid);
        __syncthreads();

        const int L = length[b];
        if (warp == 0) {
            float mx = -CUDART_INF_F;
            #pragma unroll
            for (int i = 0; i < 4; i++) {
                int s = lane + 32 * i;
                if (s >= 3 && s < 3 + L) mx = fmaxf(mx, sm.p2.sc[s]);
            }
            mx = warp_max(mx);
            float sum = 0.f;
            #pragma unroll
            for (int i = 0; i < 4; i++) {
                int s = lane + 32 * i;
                if (s >= 3 && s < 3 + L) sum += __expf(sm.p2.sc[s] - mx);
            }
            sum = warp_sum(sum);
            if (lane == 0) { sm.p2.red[0] = mx; sm.p2.red[1] = sum; }
        }
        __syncthreads();
        {
            const float mx  = sm.p2.red[0];
            const float inv = 1.0f / sm.p2.red[1];
            if (tid < S_) {
                bool v = (tid >= 3) && (tid < 3 + L);
                sm.p2.sc[tid] = v ? __expf(sm.p2.sc[tid] - mx) * inv : 0.f;
            }
        }
        __syncthreads();

        #pragma unroll
        for (int rep = 0; rep < 2; rep++) {
            const int d = tid + rep * NT;
            if (d < D_) {
                const float* col = bert + (size_t)b * (S_ * D_) + d;
                float a0 = 0.f, a1 = 0.f, a2 = 0.f, a3 = 0.f;
                #pragma unroll 1
                for (int s0 = 0; s0 < S_; s0 += 8) {
                    float x0 = col[(size_t)(s0 + 0) * D_];
                    float x1 = col[(size_t)(s0 + 1) * D_];
                    float x2 = col[(size_t)(s0 + 2) * D_];
                    float x3 = col[(size_t)(s0 + 3) * D_];
                    float x4 = col[(size_t)(s0 + 4) * D_];
                    float x5 = col[(size_t)(s0 + 5) * D_];
                    float x6 = col[(size_t)(s0 + 6) * D_];
                    float x7 = col[(size_t)(s0 + 7) * D_];
                    a0 = fmaf(sm.p2.sc[s0 + 0], x0, a0);
                    a1 = fmaf(sm.p2.sc[s0 + 1], x1, a1);
                    a2 = fmaf(sm.p2.sc[s0 + 2], x2, a2);
                    a3 = fmaf(sm.p2.sc[s0 + 3], x3, a3);
                    a0 = fmaf(sm.p2.sc[s0 + 4], x4, a0);
                    a1 = fmaf(sm.p2.sc[s0 + 5], x5, a1);
                    a2 = fmaf(sm.p2.sc[s0 + 6], x6, a2);
                    a3 = fmaf(sm.p2.sc[s0 + 7], x7, a3);
                }
                feats[(size_t)b * (2 * D_) + d] = (a0 + a1) + (a2 + a3);
            }
        }
    }

    grid_barrier();

    // ============ Phase 3: h = tanh(feats @ dense_w^T + b), f32x2 ==========
    // 128 tiles (BM=32 x BN=48). Loads use all 512 threads; compute uses
    // threads 0..255 (FMA-bound; extra warps wouldn't add issue slots).
    for (int it = blockIdx.x; it < 128; it += NB) {
        const int m0 = (it & 7) * 32;
        const int n0 = (it >> 3) * 48;
        const int tx = tid & 15;
        const int ty = (tid >> 4) & 15;
        float* Asf = (float*)sm.p3.As2u;

        unsigned long long acc0 = 0ull, acc1 = 0ull, acc2 = 0ull;

        for (int k0 = 0; k0 < KDIM; k0 += BK) {
            // A tile: 256 float4 by threads 0..255, transposed k-major
            if (tid < 256) {
                int r = tid >> 3, c = tid & 7;
                float4 v = __ldcg((const float4*)(feats + (size_t)(m0 + r) * KDIM + k0 + c * 4));
                Asf[(c * 4 + 0) * 34 + r] = v.x;
                Asf[(c * 4 + 1) * 34 + r] = v.y;
                Asf[(c * 4 + 2) * 34 + r] = v.z;
                Asf[(c * 4 + 3) * 34 + r] = v.w;
            }
            // B tile: 384 float4 by threads 128..511, duplicated pairs
            if (tid >= 128) {
                int e = tid - 128;              // 0..383
                int n = e >> 3, c = e & 7;
                float4 v = *(const float4*)(dense_w + (size_t)(n0 + n) * KDIM + k0 + c * 4);
                ((float2*)sm.p3.Bsdu)[(c * 4 + 0) * 49 + n] = make_float2(v.x, v.x);
                ((float2*)sm.p3.Bsdu)[(c * 4 + 1) * 49 + n] = make_float2(v.y, v.y);
                ((float2*)sm.p3.Bsdu)[(c * 4 + 2) * 49 + n] = make_float2(v.z, v.z);
                ((float2*)sm.p3.Bsdu)[(c * 4 + 3) * 49 + n] = make_float2(v.w, v.w);
            }
            __syncthreads();

            if (tid < 256) {
                #pragma unroll
                for (int k = 0; k < BK; k++) {
                    unsigned long long a2 = sm.p3.As2u[k * 17 + ty];
                    unsigned long long b0 = sm.p3.Bsdu[k * 49 + tx * 3 + 0];
                    unsigned long long b1 = sm.p3.Bsdu[k * 49 + tx * 3 + 1];
                    unsigned long long b2 = sm.p3.Bsdu[k * 49 + tx * 3 + 2];
                    FMA_F32X2(acc0, a2, b0);
                    FMA_F32X2(acc1, a2, b1);
                    FMA_F32X2(acc2, a2, b2);
                }
            }
            __syncthreads();
        }

        if (tid < 256) {
            unsigned long long accs[3] = {acc0, acc1, acc2};
            #pragma unroll
            for (int j = 0; j < 3; j++) {
                unsigned int lo, hi;
                asm("mov.b64 {%0, %1}, %2;" : "=r"(lo), "=r"(hi) : "l"(accs[j]));
                int n = n0 + tx * 3 + j;
                float bv = dense_b[n];
                hbuf[(size_t)(m0 + ty * 2 + 0) * NDIM + n] = tanhf(__uint_as_float(lo) + bv);
                hbuf[(size_t)(m0 + ty * 2 + 1) * NDIM + n] = tanhf(__uint_as_float(hi) + bv);
            }
        }
    }

    grid_barrier();

    // ============ Phase 4: label probs + category + head GEMMs =============
    for (int it = blockIdx.x; it < B_; it += NB) {
        const int b = it;
        __syncthreads();
        if (tid < 192)
            ((float4*)sm.p4.hs)[tid] = __ldcg((const float4*)(hbuf + (size_t)b * D_) + tid);
        __syncthreads();

        const float4* h4 = (const float4*)sm.p4.hs;

        // round 0: warps 0..15 -> labels 0..15
        {
            const int idx = warp;
            if (idx < 16) {
                const int id = c_label_ids[idx];
                const float4* r4 = (const float4*)(dec_w + (size_t)id * D_);
                float4 v0 = r4[lane];
                float4 v1 = r4[lane + 32];
                float4 v2 = r4[lane + 64];
                float4 v3 = r4[lane + 96];
                float4 v4 = r4[lane + 128];
                float4 v5 = r4[lane + 160];
                float acc = 0.f;
                acc = dot4(v0, h4[lane],       acc);
                acc = dot4(v1, h4[lane + 32],  acc);
                acc = dot4(v2, h4[lane + 64],  acc);
                acc = dot4(v3, h4[lane + 96],  acc);
                acc = dot4(v4, h4[lane + 128], acc);
                acc = dot4(v5, h4[lane + 160], acc);
                acc = warp_sum(acc);
                if (lane == 0) sm.p4.probs[idx] = tanhf(acc + dec_b[id]);
            }
        }
        // round 1: warps 0..4 -> labels 16..20; warps 6,7 -> category_out
        if (warp < 5) {
            const int idx = 16 + warp;
            const int id = c_label_ids[idx];
            const float4* r4 = (const float4*)(dec_w + (size_t)id * D_);
            float4 v0 = r4[lane];
            float4 v1 = r4[lane + 32];
            float4 v2 = r4[lane + 64];
            float4 v3 = r4[lane + 96];
            float4 v4 = r4[lane + 128];
            float4 v5 = r4[lane + 160];
            float acc = 0.f;
            acc = dot4(v0, h4[lane],       acc);
            acc = dot4(v1, h4[lane + 32],  acc);
            acc = dot4(v2, h4[lane + 64],  acc);
            acc = dot4(v3, h4[lane + 96],  acc);
            acc = dot4(v4, h4[lane + 128], acc);
            acc = dot4(v5, h4[lane + 160], acc);
            acc = warp_sum(acc);
            if (lane == 0) sm.p4.probs[idx] = tanhf(acc + dec_b[id]);
        } else if (warp == 6 || warp == 7) {
            const int w = warp - 6;
            const float4* p4 = (const float4*)(bert + (size_t)b * (S_ * D_));
            const float4* w4 = (const float4*)(senti_w + w * D_);
            float c = 0.f;
            c = dot4(p4[lane],       w4[lane],       c);
            c = dot4(p4[lane + 32],  w4[lane + 32],  c);
            c = dot4(p4[lane + 64],  w4[lane + 64],  c);
            c = dot4(p4[lane + 96],  w4[lane + 96],  c);
            c = dot4(p4[lane + 128], w4[lane + 128], c);
            c = dot4(p4[lane + 160], w4[lane + 160], c);
            c = warp_sum(c);
            if (lane == 0) d_out[b * 2 + w] = c + senti_b[w];
        }
        __syncthreads();

        if (tid < 6) {
            const int j = tid >> 1;
            const int i = tid & 1;
            const float* w   = (j == 0) ? w0 : (j == 1) ? w1 : w2;
            const int    off = (j == 0) ? 0  : (j == 1) ? 8  : 14;
            const int    n   = (j == 0) ? 8  : (j == 1) ? 6  : 7;
            float acc = 0.f;
            for (int l = 0; l < n; l++) acc += w[i * n + l] * sm.p4.probs[off + l];
            d_out[512 + b * 6 + i * 3 + j] = acc;
        }
        __syncthreads();
    }
}

// ---------------------------------------------------------------------------
extern "C" void kernel_launch(void* const* d_in, const int* in_sizes, int n_in,
                              void* d_out, int out_size)
{
    const float* bert      = (const float*)d_in[0];
    const int*   input_ids = (const int*)  d_in[1];
    const int*   length    = (const int*)  d_in[2];
    const float* senti_w   = (const float*)d_in[3];
    const float* senti_b   = (const float*)d_in[4];
    const float* dense_w   = (const float*)d_in[5];
    const float* dense_b   = (const float*)d_in[6];
    const float* dec_w     = (const float*)d_in[7];
    const float* dec_b     = (const float*)d_in[8];
    const float* w0        = (const float*)d_in[9];
    const float* w1        = (const float*)d_in[10];
    const float* w2        = (const float*)d_in[11];
    float* out = (float*)d_out;

    float* feats; cudaGetSymbolAddress((void**)&feats, g_feats);
    float* hbuf;  cudaGetSymbolAddress((void**)&hbuf,  g_h);
    float* sraw;  cudaGetSymbolAddress((void**)&sraw,  g_sraw);

    fused_all<<<NB, NT>>>(bert, input_ids, length, senti_w, senti_b,
                          dense_w, dense_b, dec_w, dec_b, w0, w1, w2,
                          out, feats, hbuf, sraw);
}

// round 15
// speedup vs baseline: 1.1530x; 1.1530x over previous
#include <cuda_runtime.h>
#include <cuda_bf16.h>
#include <math_constants.h>

#define B_  256
#define S_  128
#define D_  768
#define MASK_ID_ 103

// Scratch (no allocation allowed -> device globals)
__device__ float g_feats[B_ * 2 * D_];   // [att | mask_logits], 256 x 1536
__device__ float g_h[B_ * D_];           // tanh(dense) output, 256 x 768
__device__ float g_sraw[B_ * S_];        // raw scores, 256 x 128

__constant__ int c_label_ids[21] = {
    2307, 2204, 3835, 2157, 6581, 2986, 5151, 3893,
    7929, 24791, 8699, 4257, 16021, 6623,
    6659, 2919, 11771, 3532, 11325, 4997, 13135
};

__device__ __forceinline__ float warp_sum(float v) {
    #pragma unroll
    for (int o = 16; o; o >>= 1) v += __shfl_xor_sync(0xffffffffu, v, o);
    return v;
}
__device__ __forceinline__ float warp_max(float v) {
    #pragma unroll
    for (int o = 16; o; o >>= 1) v = fmaxf(v, __shfl_xor_sync(0xffffffffu, v, o));
    return v;
}

#define FMA_F32X2(acc, a, b) \
    asm("fma.rn.f32x2 %0, %1, %2, %0;" : "+l"(acc) : "l"(a), "l"(b))

__device__ __forceinline__ float dot4(float4 a, float4 b, float acc) {
    return fmaf(a.x, b.x, fmaf(a.y, b.y, fmaf(a.z, b.z, fmaf(a.w, b.w, acc))));
}

// ---------------------------------------------------------------------------
// Kernel 1a: scores_raw[b,s] = dot(bert[b,s,:], bert[b,mpos,:])
// grid = (16 s-chunks, 256 batches), block = 256: one warp per row.
// (256,3): ~85-reg budget keeps the 6 LDG.128 batched in SASS.
// Chunk 0 also writes feats[b][D:2D] = mask_logits.
// ---------------------------------------------------------------------------
__global__ __launch_bounds__(256, 3) void k1a_scores(
    const float* __restrict__ bert,
    const int*   __restrict__ input_ids,
    float*       __restrict__ feats,
    float*       __restrict__ sraw_g)
{
    const int b    = blockIdx.y;
    const int tid  = threadIdx.x;
    const int warp = tid >> 5;
    const int lane = tid & 31;

    __shared__ float ml[D_];
    __shared__ int   mpos;

    if (tid == 0) mpos = 0x7fffffff;
    __syncthreads();
    if (tid < S_ && input_ids[b * S_ + tid] == MASK_ID_) atomicMin(&mpos, tid);
    __syncthreads();
    const int mp = mpos;

    const float* base = bert + (size_t)b * (S_ * D_);

    if (tid < 192)
        ((float4*)ml)[tid] = ((const float4*)(base + (size_t)mp * D_))[tid];
    __syncthreads();

    const int s = blockIdx.x * 8 + warp;
    const float4* r4 = (const float4*)(base + (size_t)s * D_);
    const float4* m4 = (const float4*)ml;

    float4 v0 = r4[lane];
    float4 v1 = r4[lane + 32];
    float4 v2 = r4[lane + 64];
    float4 v3 = r4[lane + 96];
    float4 v4 = r4[lane + 128];
    float4 v5 = r4[lane + 160];

    float acc = 0.f;
    acc = dot4(v0, m4[lane],       acc);
    acc = dot4(v1, m4[lane + 32],  acc);
    acc = dot4(v2, m4[lane + 64],  acc);
    acc = dot4(v3, m4[lane + 96],  acc);
    acc = dot4(v4, m4[lane + 128], acc);
    acc = dot4(v5, m4[lane + 160], acc);
    acc = warp_sum(acc);
    if (lane == 0) sraw_g[b * S_ + s] = acc;

    if (blockIdx.x == 0 && tid < 192)
        ((float4*)(feats + (size_t)b * (2 * D_) + D_))[tid] = m4[tid];
}

// ---------------------------------------------------------------------------
// Kernel 1b: softmax + att, FLOAT4 columns.
// grid = (2 chunks of 96 float4-cols, 256 batches), block = 96.
// (96,8): 85-reg budget; batches of 8 float4 loads = 32 data regs in flight
// (4KB per warp). 24 warps/SM -> demand >> HBM; truly bandwidth-limited.
// ---------------------------------------------------------------------------
__global__ __launch_bounds__(96, 8) void k1b_att(
    const float* __restrict__ bert,
    const int*   __restrict__ length,
    const float* __restrict__ sraw_g,
    float*       __restrict__ feats)
{
    const int b     = blockIdx.y;
    const int chunk = blockIdx.x;      // 0 or 1
    const int tid   = threadIdx.x;     // 0..95
    const int warp  = tid >> 5;
    const int lane  = tid & 31;

    __shared__ float sc[S_];
    __shared__ float red[2];

    for (int i = tid; i < S_; i += 96) sc[i] = sraw_g[b * S_ + i];
    __syncthreads();

    const int L = length[b];
    if (warp == 0) {
        float mx = -CUDART_INF_F;
        #pragma unroll
        for (int i = 0; i < 4; i++) {
            int s = lane + 32 * i;
            if (s >= 3 && s < 3 + L) mx = fmaxf(mx, sc[s]);
        }
        mx = warp_max(mx);
        float sum = 0.f;
        #pragma unroll
        for (int i = 0; i < 4; i++) {
            int s = lane + 32 * i;
            if (s >= 3 && s < 3 + L) sum += __expf(sc[s] - mx);
        }
        sum = warp_sum(sum);
        if (lane == 0) { red[0] = mx; red[1] = sum; }
    }
    __syncthreads();
    {
        const float mx  = red[0];
        const float inv = 1.0f / red[1];
        for (int i = tid; i < S_; i += 96) {
            bool v = (i >= 3) && (i < 3 + L);
            sc[i] = v ? __expf(sc[i] - mx) * inv : 0.f;
        }
    }
    __syncthreads();

    // one float4 column per thread: 128 rows, stride 192 float4s (3KB)
    const float4* colp = (const float4*)(bert + (size_t)b * (S_ * D_))
                         + chunk * 96 + tid;
    float4 accA = make_float4(0.f, 0.f, 0.f, 0.f);
    float4 accB = make_float4(0.f, 0.f, 0.f, 0.f);

    #pragma unroll 1
    for (int s0 = 0; s0 < S_; s0 += 8) {
        float4 x[8];
        #pragma unroll
        for (int k = 0; k < 8; k++)
            x[k] = colp[(size_t)(s0 + k) * 192];
        #pragma unroll
        for (int k = 0; k < 8; k += 2) {
            const float w0 = sc[s0 + k];
            const float w1 = sc[s0 + k + 1];
            accA.x = fmaf(w0, x[k].x, accA.x);
            accA.y = fmaf(w0, x[k].y, accA.y);
            accA.z = fmaf(w0, x[k].z, accA.z);
            accA.w = fmaf(w0, x[k].w, accA.w);
            accB.x = fmaf(w1, x[k + 1].x, accB.x);
            accB.y = fmaf(w1, x[k + 1].y, accB.y);
            accB.z = fmaf(w1, x[k + 1].z, accB.z);
            accB.w = fmaf(w1, x[k + 1].w, accB.w);
        }
    }

    float4 r;
    r.x = accA.x + accB.x;
    r.y = accA.y + accB.y;
    r.z = accA.z + accB.z;
    r.w = accA.w + accB.w;
    ((float4*)(feats + (size_t)b * (2 * D_)))[chunk * 96 + tid] = r;
}

// ---------------------------------------------------------------------------
// Kernel 2: h = tanh(feats @ dense_w^T + dense_b) via packed fma.rn.f32x2.
// M=256, N=768, K=1536. BM=32, BN=48, BK=32; grid 8x16 = 128 CTAs.
// Own launch -> own register allocation (no cross-phase cap).
// ---------------------------------------------------------------------------
#define BM 32
#define BN 48
#define BK 32
#define KDIM 1536
#define NDIM 768

__global__ __launch_bounds__(256) void k2_dense(
    const float* __restrict__ A,
    const float* __restrict__ Bw,
    const float* __restrict__ bias,
    float*       __restrict__ H)
{
    __shared__ unsigned long long As2u[BK * 17];
    __shared__ unsigned long long Bsdu[BK * 49];

    const int m0  = blockIdx.x * BM;
    const int n0  = blockIdx.y * BN;
    const int tid = threadIdx.x;
    const int tx  = tid & 15;
    const int ty  = tid >> 4;

    float* Asf = (float*)As2u;

    unsigned long long acc0 = 0ull, acc1 = 0ull, acc2 = 0ull;

    for (int k0 = 0; k0 < KDIM; k0 += BK) {
        {
            int r = tid >> 3, c = tid & 7;
            float4 v = *(const float4*)(A + (size_t)(m0 + r) * KDIM + k0 + c * 4);
            Asf[(c * 4 + 0) * 34 + r] = v.x;
            Asf[(c * 4 + 1) * 34 + r] = v.y;
            Asf[(c * 4 + 2) * 34 + r] = v.z;
            Asf[(c * 4 + 3) * 34 + r] = v.w;
        }
        {
            int n = tid >> 3, c = tid & 7;
            float4 v = *(const float4*)(Bw + (size_t)(n0 + n) * KDIM + k0 + c * 4);
            ((float2*)Bsdu)[(c * 4 + 0) * 49 + n] = make_float2(v.x, v.x);
            ((float2*)Bsdu)[(c * 4 + 1) * 49 + n] = make_float2(v.y, v.y);
            ((float2*)Bsdu)[(c * 4 + 2) * 49 + n] = make_float2(v.z, v.z);
            ((float2*)Bsdu)[(c * 4 + 3) * 49 + n] = make_float2(v.w, v.w);
            if (tid < 128) {
                int idx = tid + 256;
                n = idx >> 3; c = idx & 7;
                float4 w = *(const float4*)(Bw + (size_t)(n0 + n) * KDIM + k0 + c * 4);
                ((float2*)Bsdu)[(c * 4 + 0) * 49 + n] = make_float2(w.x, w.x);
                ((float2*)Bsdu)[(c * 4 + 1) * 49 + n] = make_float2(w.y, w.y);
                ((float2*)Bsdu)[(c * 4 + 2) * 49 + n] = make_float2(w.z, w.z);
                ((float2*)Bsdu)[(c * 4 + 3) * 49 + n] = make_float2(w.w, w.w);
            }
        }
        __syncthreads();

        #pragma unroll
        for (int k = 0; k < BK; k++) {
            unsigned long long a2 = As2u[k * 17 + ty];
            unsigned long long b0 = Bsdu[k * 49 + tx * 3 + 0];
            unsigned long long b1 = Bsdu[k * 49 + tx * 3 + 1];
            unsigned long long b2 = Bsdu[k * 49 + tx * 3 + 2];
            FMA_F32X2(acc0, a2, b0);
            FMA_F32X2(acc1, a2, b1);
            FMA_F32X2(acc2, a2, b2);
        }
        __syncthreads();
    }

    unsigned long long accs[3] = {acc0, acc1, acc2};
    #pragma unroll
    for (int j = 0; j < 3; j++) {
        unsigned int lo, hi;
        asm("mov.b64 {%0, %1}, %2;" : "=r"(lo), "=r"(hi) : "l"(accs[j]));
        int n = n0 + tx * 3 + j;
        float bv = bias[n];
        H[(size_t)(m0 + ty * 2 + 0) * NDIM + n] = tanhf(__uint_as_float(lo) + bv);
        H[(size_t)(m0 + ty * 2 + 1) * NDIM + n] = tanhf(__uint_as_float(hi) + bv);
    }
}

// ---------------------------------------------------------------------------
// Kernel 3: 21 label-prob dots (warps 0..20) + category_out (warp 21) +
// tiny head GEMMs. block = 704 (22 warps). Measured 6.9us.
// ---------------------------------------------------------------------------
__global__ __launch_bounds__(704) void k3_decoder(
    const float* __restrict__ h,
    const float* __restrict__ dec_w,
    const float* __restrict__ dec_b,
    const float* __restrict__ bert,
    const float* __restrict__ senti_w,
    const float* __restrict__ senti_b,
    const float* __restrict__ w0,
    const float* __restrict__ w1,
    const float* __restrict__ w2,
    float*       __restrict__ d_out)
{
    const int b    = blockIdx.x;
    const int tid  = threadIdx.x;
    const int warp = tid >> 5;
    const int lane = tid & 31;

    __shared__ float hs[D_];
    __shared__ float probs[21];

    if (tid < 192)
        ((float4*)hs)[tid] = ((const float4*)(h + (size_t)b * D_))[tid];
    __syncthreads();

    if (warp < 21) {
        const int id = c_label_ids[warp];
        const float4* r4 = (const float4*)(dec_w + (size_t)id * D_);
        const float4* h4 = (const float4*)hs;
        float4 v0 = r4[lane];
        float4 v1 = r4[lane + 32];
        float4 v2 = r4[lane + 64];
        float4 v3 = r4[lane + 96];
        float4 v4 = r4[lane + 128];
        float4 v5 = r4[lane + 160];
        float acc = 0.f;
        acc = dot4(v0, h4[lane],       acc);
        acc = dot4(v1, h4[lane + 32],  acc);
        acc = dot4(v2, h4[lane + 64],  acc);
        acc = dot4(v3, h4[lane + 96],  acc);
        acc = dot4(v4, h4[lane + 128], acc);
        acc = dot4(v5, h4[lane + 160], acc);
        acc = warp_sum(acc);
        if (lane == 0) probs[warp] = tanhf(acc + dec_b[id]);
    } else {
        const float4* p4 = (const float4*)(bert + (size_t)b * (S_ * D_));
        float4 p0 = p4[lane],      p1 = p4[lane + 32],  p2 = p4[lane + 64];
        float4 p3 = p4[lane + 96], p4v = p4[lane + 128], p5 = p4[lane + 160];
        #pragma unroll
        for (int w = 0; w < 2; w++) {
            const float4* w4 = (const float4*)(senti_w + w * D_);
            float c = 0.f;
            c = dot4(p0, w4[lane],       c);
            c = dot4(p1, w4[lane + 32],  c);
            c = dot4(p2, w4[lane + 64],  c);
            c = dot4(p3, w4[lane + 96],  c);
            c = dot4(p4v, w4[lane + 128], c);
            c = dot4(p5, w4[lane + 160], c);
            c = warp_sum(c);
            if (lane == 0) d_out[b * 2 + w] = c + senti_b[w];
        }
    }
    __syncthreads();

    if (tid < 6) {
        const int j = tid >> 1;
        const int i = tid & 1;
        const float* w   = (j == 0) ? w0 : (j == 1) ? w1 : w2;
        const int    off = (j == 0) ? 0  : (j == 1) ? 8  : 14;
        const int    n   = (j == 0) ? 8  : (j == 1) ? 6  : 7;
        float acc = 0.f;
        for (int l = 0; l < n; l++) acc += w[i * n + l] * probs[off + l];
        d_out[512 + b * 6 + i * 3 + j] = acc;
    }
}

// ---------------------------------------------------------------------------
extern "C" void kernel_launch(void* const* d_in, const int* in_sizes, int n_in,
                              void* d_out, int out_size)
{
    const float* bert      = (const float*)d_in[0];
    const int*   input_ids = (const int*)  d_in[1];
    const int*   length    = (const int*)  d_in[2];
    const float* senti_w   = (const float*)d_in[3];
    const float* senti_b   = (const float*)d_in[4];
    const float* dense_w   = (const float*)d_in[5];
    const float* dense_b   = (const float*)d_in[6];
    const float* dec_w     = (const float*)d_in[7];
    const float* dec_b     = (const float*)d_in[8];
    const float* w0        = (const float*)d_in[9];
    const float* w1        = (const float*)d_in[10];
    const float* w2        = (const float*)d_in[11];
    float* out = (float*)d_out;

    float* feats; cudaGetSymbolAddress((void**)&feats, g_feats);
    float* hbuf;  cudaGetSymbolAddress((void**)&hbuf,  g_h);
    float* sraw;  cudaGetSymbolAddress((void**)&sraw,  g_sraw);

    k1a_scores<<<dim3(16, B_), 256>>>(bert, input_ids, feats, sraw);
    k1b_att   <<<dim3(2, B_), 96>>>(bert, length, sraw, feats);
    k2_dense  <<<dim3(B_ / BM, NDIM / BN), 256>>>(feats, dense_w, dense_b, hbuf);
    k3_decoder<<<B_, 704>>>(hbuf, dec_w, dec_b, bert, senti_w, senti_b, w0, w1, w2, out);
}